// round 10
// baseline (speedup 1.0000x reference)
#include <cuda_runtime.h>
#include <cuda_bf16.h>
#include <cuda_fp16.h>
#include <math.h>
#include <cstdint>

#define NN   50000
#define EE   800000
#define PP   65536
#define LDA  40
#define MTG  782          // ceil(50000/64) gemm blocks in fused kernels
#define HOPB 6250         // 50000/8 hop blocks

// ====================== scratch ======================

__device__ int   g_cnt[2 * NN + 64];      // [0,NN)=deg, [NN,2NN)=fill, [2NN,+64)=chain
__device__ float g_dn[NN];
__device__ int   g_rp[NN + 1];
__device__ __align__(16) int2 g_csr[EE];
__device__ __align__(16) float g_acc[NN * 128];
__device__ __align__(16) __half g_x16 [NN * 128];
__device__ __align__(16) __half g_hop1[NN * 128];
__device__ __align__(16) __half g_hop2[NN * 128];
__device__ __align__(16) __half g_hop3[NN * 128];
__device__ __align__(16) __half g_hA  [NN * 128];
__device__ __align__(16) __half g_hB  [NN * 128];
__device__ __align__(16) __half g_g   [NN * 256];
__device__ __align__(16) __half g_wt1[65536];
__device__ __align__(16) __half g_wt2[65536];
__device__ __align__(16) __half g_wt3[32768];

// ====================== helpers ======================

__device__ __forceinline__ uint32_t smem_u32(const void* p) {
    uint32_t a;
    asm("{ .reg .u64 t; cvta.to.shared.u64 t, %1; cvt.u32.u64 %0, t; }" : "=r"(a) : "l"(p));
    return a;
}

__device__ __forceinline__ void ldsm4(uint32_t* r, uint32_t addr) {
    asm volatile("ldmatrix.sync.aligned.m8n8.x4.shared.b16 {%0,%1,%2,%3}, [%4];"
                 : "=r"(r[0]), "=r"(r[1]), "=r"(r[2]), "=r"(r[3]) : "r"(addr));
}

__device__ __forceinline__ void mma16816f(float* c, const uint32_t* a, const uint32_t* b) {
    asm volatile(
        "mma.sync.aligned.m16n8k16.row.col.f32.f16.f16.f32 "
        "{%0,%1,%2,%3}, {%4,%5,%6,%7}, {%8,%9}, {%0,%1,%2,%3};"
        : "+f"(c[0]), "+f"(c[1]), "+f"(c[2]), "+f"(c[3])
        : "r"(a[0]), "r"(a[1]), "r"(a[2]), "r"(a[3]), "r"(b[0]), "r"(b[1]));
}

__device__ __forceinline__ void cpasync16(uint32_t saddr, const void* gptr) {
    asm volatile("cp.async.cg.shared.global [%0], [%1], 16;" :: "r"(saddr), "l"(gptr));
}
__device__ __forceinline__ void cpasync_commit() {
    asm volatile("cp.async.commit_group;" ::: "memory");
}
template <int N>
__device__ __forceinline__ void cpasync_wait() {
    asm volatile("cp.async.wait_group %0;" :: "n"(N) : "memory");
}

// ====================== launch 2: prep + hist fused ======================
// (launch 1 is a memset of g_cnt)

__global__ void k_prep2(const float* __restrict__ x,
                        const float* __restrict__ W1, const float* __restrict__ W2,
                        const float* __restrict__ W3, const int* __restrict__ dst) {
    int gid = blockIdx.x * 256 + threadIdx.x;
    if (gid < EE) atomicAdd(&g_cnt[dst[gid]], 1);
    if (gid < 65536) {
        int n = gid >> 9, k = gid & 511;
        g_wt1[gid] = __float2half_rn(W1[k * 128 + n]);
    } else if (gid < 131072) {
        int idx = gid - 65536;
        int n = idx >> 9, k = idx & 511;
        g_wt2[idx] = __float2half_rn(W2[k * 128 + n]);
    } else if (gid < 163840) {
        int idx = gid - 131072;
        int r = idx >> 7, k = idx & 127;
        int j = r >> 6, n = r & 63;
        g_wt3[idx] = __float2half_rn(W3[(j * 128 + k) * 64 + n]);
    }
    if (gid < NN * 32) {
        float4 v = __ldg((const float4*)x + gid);
        __half2 a = __floats2half2_rn(v.x, v.y);
        __half2 b = __floats2half2_rn(v.z, v.w);
        ((uint2*)g_x16)[gid] = make_uint2(*(uint32_t*)&a, *(uint32_t*)&b);
    }
}

// ====================== launch 3: single-pass chained scan + dn ============

__global__ void __launch_bounds__(1024)
k_scanchain() {
    __shared__ int s[1024];
    __shared__ int sprev;
    volatile int* chain = (volatile int*)(g_cnt + 2 * NN);
    int b = blockIdx.x;
    int i = b * 1024 + threadIdx.x;
    int v = (i < NN) ? g_cnt[i] : 0;
    s[threadIdx.x] = v;
    __syncthreads();
    #pragma unroll
    for (int off = 1; off < 1024; off <<= 1) {
        int t = (threadIdx.x >= off) ? s[threadIdx.x - off] : 0;
        __syncthreads();
        s[threadIdx.x] += t;
        __syncthreads();
    }
    if (threadIdx.x == 0) {
        int prev = 0;
        if (b > 0) {
            int t;
            do { t = chain[b - 1]; } while (t == 0);
            prev = t - 1;
        }
        sprev = prev;
        __threadfence();
        chain[b] = prev + s[1023] + 1;
    }
    __syncthreads();
    int prev = sprev;
    if (i < NN) {
        g_rp[i + 1] = s[threadIdx.x] + prev;
        if (i == 0) g_rp[0] = 0;
        int d = (v < 1) ? 1 : v;
        g_dn[i] = rsqrtf((float)d);
    }
}

// ====================== launch 4: scatter to interleaved CSR ================

__global__ void k_scatter(const int* __restrict__ src, const int* __restrict__ dst,
                          const float* __restrict__ w) {
    int e = blockIdx.x * blockDim.x + threadIdx.x;
    if (e >= EE) return;
    int s = src[e], d = dst[e];
    int slot = g_rp[d] + atomicAdd(&g_cnt[NN + d], 1);
    float cw = w[e] * g_dn[s] * g_dn[d];
    g_csr[slot] = make_int2(s, __float_as_int(cw));
}

// ====================== fused hop (width 128) + partial GEMM ================
// blocks [0,MTG):  g_acc (+)= gin[64 rows x 128] @ Wt[:, kOff:kOff+128]^T (64x128 tile)
// blocks [MTG,..): hout = C * hin (warp per row, MLP-4)

template <int FIRST>
__global__ void __launch_bounds__(256, 2)
k_hopgemm(const __half* __restrict__ hin, __half* __restrict__ hout,
          const __half* __restrict__ gin, const __half* __restrict__ Wt, int kOff) {
    __shared__ __half As[2][64 * LDA];
    __shared__ __half Bs[2][128 * LDA];
    int tid = threadIdx.x, warp = tid >> 5, lane = tid & 31;

    if (blockIdx.x >= MTG) {
        // ---------------- hop ----------------
        int gw = (blockIdx.x - MTG) * 8 + warp;
        if (gw >= NN) return;
        int beg = g_rp[gw], end = g_rp[gw + 1];
        const uint2* in = (const uint2*)hin;
        float4 acc = make_float4(0.f, 0.f, 0.f, 0.f);
        int e = beg;
        for (; e + 4 <= end; e += 4) {
            int2 p0 = __ldg(&g_csr[e + 0]);
            int2 p1 = __ldg(&g_csr[e + 1]);
            int2 p2 = __ldg(&g_csr[e + 2]);
            int2 p3 = __ldg(&g_csr[e + 3]);
            uint2 v0 = __ldg(&in[(size_t)p0.x * 32 + lane]);
            uint2 v1 = __ldg(&in[(size_t)p1.x * 32 + lane]);
            uint2 v2 = __ldg(&in[(size_t)p2.x * 32 + lane]);
            uint2 v3 = __ldg(&in[(size_t)p3.x * 32 + lane]);
            float w0 = __int_as_float(p0.y), w1 = __int_as_float(p1.y);
            float w2 = __int_as_float(p2.y), w3 = __int_as_float(p3.y);
            float2 a0 = __half22float2(*(__half2*)&v0.x), b0 = __half22float2(*(__half2*)&v0.y);
            float2 a1 = __half22float2(*(__half2*)&v1.x), b1 = __half22float2(*(__half2*)&v1.y);
            float2 a2 = __half22float2(*(__half2*)&v2.x), b2 = __half22float2(*(__half2*)&v2.y);
            float2 a3 = __half22float2(*(__half2*)&v3.x), b3 = __half22float2(*(__half2*)&v3.y);
            acc.x = fmaf(w0, a0.x, acc.x); acc.y = fmaf(w0, a0.y, acc.y);
            acc.z = fmaf(w0, b0.x, acc.z); acc.w = fmaf(w0, b0.y, acc.w);
            acc.x = fmaf(w1, a1.x, acc.x); acc.y = fmaf(w1, a1.y, acc.y);
            acc.z = fmaf(w1, b1.x, acc.z); acc.w = fmaf(w1, b1.y, acc.w);
            acc.x = fmaf(w2, a2.x, acc.x); acc.y = fmaf(w2, a2.y, acc.y);
            acc.z = fmaf(w2, b2.x, acc.z); acc.w = fmaf(w2, b2.y, acc.w);
            acc.x = fmaf(w3, a3.x, acc.x); acc.y = fmaf(w3, a3.y, acc.y);
            acc.z = fmaf(w3, b3.x, acc.z); acc.w = fmaf(w3, b3.y, acc.w);
        }
        for (; e < end; e++) {
            int2 p = __ldg(&g_csr[e]);
            float w = __int_as_float(p.y);
            uint2 v = __ldg(&in[(size_t)p.x * 32 + lane]);
            float2 f0 = __half22float2(*(__half2*)&v.x);
            float2 f1 = __half22float2(*(__half2*)&v.y);
            acc.x = fmaf(w, f0.x, acc.x);
            acc.y = fmaf(w, f0.y, acc.y);
            acc.z = fmaf(w, f1.x, acc.z);
            acc.w = fmaf(w, f1.y, acc.w);
        }
        __half2 o0 = __floats2half2_rn(acc.x, acc.y);
        __half2 o1 = __floats2half2_rn(acc.z, acc.w);
        ((uint2*)hout)[(size_t)gw * 32 + lane] = make_uint2(*(uint32_t*)&o0, *(uint32_t*)&o1);
        return;
    }

    // ---------------- partial GEMM (64 x 128 tile, K=128) ----------------
    int row0 = blockIdx.x * 64;
    int mw = warp & 1, nw = warp >> 1;

    float acc[2][4][4];
    #pragma unroll
    for (int i = 0; i < 2; i++)
        #pragma unroll
        for (int j = 0; j < 4; j++)
            #pragma unroll
            for (int q = 0; q < 4; q++) acc[i][j][q] = 0.f;

    int lr = tid >> 2, lj = tid & 3;
    int lr2 = (tid + 256) >> 2;

    auto load_stage = [&](int buf, int s) {
        uint32_t sA = smem_u32(&As[buf][0]);
        uint32_t sB = smem_u32(&Bs[buf][0]);
        int g = row0 + lr; if (g > NN - 1) g = NN - 1;
        cpasync16(sA + (uint32_t)(lr * LDA + lj * 8) * 2,
                  gin + (size_t)g * 128 + s * 32 + lj * 8);
        cpasync16(sB + (uint32_t)(lr * LDA + lj * 8) * 2,
                  Wt + (size_t)lr * 512 + kOff + s * 32 + lj * 8);
        cpasync16(sB + (uint32_t)(lr2 * LDA + lj * 8) * 2,
                  Wt + (size_t)lr2 * 512 + kOff + s * 32 + lj * 8);
    };

    load_stage(0, 0);
    cpasync_commit();

    #pragma unroll 1
    for (int s = 0; s < 4; s++) {
        int buf = s & 1;
        cpasync_wait<0>();
        __syncthreads();
        if (s + 1 < 4) {
            load_stage(buf ^ 1, s + 1);
            cpasync_commit();
        }
        uint32_t sA = smem_u32(&As[buf][0]);
        uint32_t sB = smem_u32(&Bs[buf][0]);
        #pragma unroll
        for (int kk = 0; kk < 2; kk++) {
            int akoff = kk * 16 + ((lane >> 4) << 3);
            int lrow = lane & 15;
            uint32_t a[2][4];
            #pragma unroll
            for (int fi = 0; fi < 2; fi++) {
                uint32_t off = (uint32_t)(((32 * mw + 16 * fi + lrow) * LDA + akoff) * 2);
                ldsm4(a[fi], sA + off);
            }
            uint32_t b[4][2];
            #pragma unroll
            for (int fj2 = 0; fj2 < 2; fj2++) {
                uint32_t off = (uint32_t)(((32 * nw + 16 * fj2 + lrow) * LDA + akoff) * 2);
                uint32_t t[4];
                ldsm4(t, sB + off);
                b[2 * fj2][0] = t[0]; b[2 * fj2][1] = t[2];
                b[2 * fj2 + 1][0] = t[1]; b[2 * fj2 + 1][1] = t[3];
            }
            #pragma unroll
            for (int fi = 0; fi < 2; fi++)
                #pragma unroll
                for (int fj = 0; fj < 4; fj++)
                    mma16816f(acc[fi][fj], a[fi], b[fj]);
        }
        __syncthreads();
    }

    #pragma unroll
    for (int fi = 0; fi < 2; fi++) {
        #pragma unroll
        for (int fj = 0; fj < 4; fj++) {
            int mrow = row0 + 32 * mw + 16 * fi + (lane >> 2);
            int col  = 32 * nw + 8 * fj + 2 * (lane & 3);
            #pragma unroll
            for (int h = 0; h < 2; h++) {
                int r = mrow + 8 * h;
                if (r < NN) {
                    float2* p = (float2*)(g_acc + (size_t)r * 128 + col);
                    float2 v = make_float2(acc[fi][fj][2 * h + 0], acc[fi][fj][2 * h + 1]);
                    if (!FIRST) { float2 o = *p; v.x += o.x; v.y += o.y; }
                    *p = v;
                }
            }
        }
    }
}

// ====================== final GEMM: chunk3 + acc + bias + relu ==============
// 128x128 tile, K=128, reads g_acc, writes fp16

__global__ void __launch_bounds__(256, 1)
k_mfinal(const __half* __restrict__ f, const __half* __restrict__ Wt, int kOff,
         const float* __restrict__ bias, __half* __restrict__ out) {
    __shared__ __half As[2][128 * LDA];
    __shared__ __half Bs[2][128 * LDA];

    int tid = threadIdx.x, warp = tid >> 5, lane = tid & 31;
    int mw = warp & 1, nw = warp >> 1;
    int row0 = blockIdx.x * 128;

    int lr = tid >> 2, lj = tid & 3;
    int lr2 = (tid + 256) >> 2;

    float acc[4][4][4];
    #pragma unroll
    for (int i = 0; i < 4; i++)
        #pragma unroll
        for (int j = 0; j < 4; j++)
            #pragma unroll
            for (int q = 0; q < 4; q++) acc[i][j][q] = 0.f;

    auto load_stage = [&](int buf, int s) {
        uint32_t sA = smem_u32(&As[buf][0]);
        uint32_t sB = smem_u32(&Bs[buf][0]);
        int g0 = row0 + lr;  if (g0 > NN - 1) g0 = NN - 1;
        int g1 = row0 + lr2; if (g1 > NN - 1) g1 = NN - 1;
        cpasync16(sA + (uint32_t)(lr * LDA + lj * 8) * 2,
                  f + (size_t)g0 * 128 + s * 32 + lj * 8);
        cpasync16(sA + (uint32_t)(lr2 * LDA + lj * 8) * 2,
                  f + (size_t)g1 * 128 + s * 32 + lj * 8);
        cpasync16(sB + (uint32_t)(lr * LDA + lj * 8) * 2,
                  Wt + (size_t)lr * 512 + kOff + s * 32 + lj * 8);
        cpasync16(sB + (uint32_t)(lr2 * LDA + lj * 8) * 2,
                  Wt + (size_t)lr2 * 512 + kOff + s * 32 + lj * 8);
    };

    load_stage(0, 0);
    cpasync_commit();

    #pragma unroll 1
    for (int s = 0; s < 4; s++) {
        int buf = s & 1;
        cpasync_wait<0>();
        __syncthreads();
        if (s + 1 < 4) {
            load_stage(buf ^ 1, s + 1);
            cpasync_commit();
        }
        uint32_t sA = smem_u32(&As[buf][0]);
        uint32_t sB = smem_u32(&Bs[buf][0]);
        #pragma unroll
        for (int kk = 0; kk < 2; kk++) {
            int akoff = kk * 16 + ((lane >> 4) << 3);
            int lrow = lane & 15;
            uint32_t a[4][4];
            #pragma unroll
            for (int fi = 0; fi < 4; fi++) {
                uint32_t off = (uint32_t)(((64 * mw + 16 * fi + lrow) * LDA + akoff) * 2);
                ldsm4(a[fi], sA + off);
            }
            uint32_t b[4][2];
            #pragma unroll
            for (int fj2 = 0; fj2 < 2; fj2++) {
                uint32_t off = (uint32_t)(((32 * nw + 16 * fj2 + lrow) * LDA + akoff) * 2);
                uint32_t t[4];
                ldsm4(t, sB + off);
                b[2 * fj2][0] = t[0]; b[2 * fj2][1] = t[2];
                b[2 * fj2 + 1][0] = t[1]; b[2 * fj2 + 1][1] = t[3];
            }
            #pragma unroll
            for (int fi = 0; fi < 4; fi++)
                #pragma unroll
                for (int fj = 0; fj < 4; fj++)
                    mma16816f(acc[fi][fj], a[fi], b[fj]);
        }
        __syncthreads();
    }

    #pragma unroll
    for (int fi = 0; fi < 4; fi++) {
        #pragma unroll
        for (int fj = 0; fj < 4; fj++) {
            int mrow = row0 + 64 * mw + 16 * fi + (lane >> 2);
            int col  = 32 * nw + 8 * fj + 2 * (lane & 3);
            #pragma unroll
            for (int h = 0; h < 2; h++) {
                int r = mrow + 8 * h;
                if (r < NN) {
                    float2 av = *(float2*)(g_acc + (size_t)r * 128 + col);
                    float v0 = acc[fi][fj][2 * h + 0] + av.x + bias[col];
                    float v1 = acc[fi][fj][2 * h + 1] + av.y + bias[col + 1];
                    v0 = v0 > 0.f ? v0 : 0.f;
                    v1 = v1 > 0.f ? v1 : 0.f;
                    *(__half2*)(out + (size_t)r * 128 + col) = __floats2half2_rn(v0, v1);
                }
            }
        }
    }
}

// ====================== layer-3 GEMM (hB @ W3 -> gg, 256 cols) ==============

__global__ void __launch_bounds__(256, 1)
k_mgemm3(const __half* __restrict__ f, const __half* __restrict__ Wt,
         const float* __restrict__ bias, __half* __restrict__ out) {
    __shared__ __half As[2][128 * LDA];
    __shared__ __half Bs[2][128 * LDA];

    int tid = threadIdx.x, warp = tid >> 5, lane = tid & 31;
    int mw = warp & 1, nw = warp >> 1;
    int row0 = blockIdx.x * 128;
    int rbase = blockIdx.y * 128;

    int lr = tid >> 2, lj = tid & 3;
    int lr2 = (tid + 256) >> 2;

    float acc[4][4][4];
    #pragma unroll
    for (int i = 0; i < 4; i++)
        #pragma unroll
        for (int j = 0; j < 4; j++)
            #pragma unroll
            for (int q = 0; q < 4; q++) acc[i][j][q] = 0.f;

    auto load_stage = [&](int buf, int s) {
        uint32_t sA = smem_u32(&As[buf][0]);
        uint32_t sB = smem_u32(&Bs[buf][0]);
        int g0 = row0 + lr;  if (g0 > NN - 1) g0 = NN - 1;
        int g1 = row0 + lr2; if (g1 > NN - 1) g1 = NN - 1;
        cpasync16(sA + (uint32_t)(lr * LDA + lj * 8) * 2,
                  f + (size_t)g0 * 128 + s * 32 + lj * 8);
        cpasync16(sA + (uint32_t)(lr2 * LDA + lj * 8) * 2,
                  f + (size_t)g1 * 128 + s * 32 + lj * 8);
        cpasync16(sB + (uint32_t)(lr * LDA + lj * 8) * 2,
                  Wt + (size_t)(rbase + lr) * 128 + s * 32 + lj * 8);
        cpasync16(sB + (uint32_t)(lr2 * LDA + lj * 8) * 2,
                  Wt + (size_t)(rbase + lr2) * 128 + s * 32 + lj * 8);
    };

    load_stage(0, 0);
    cpasync_commit();

    #pragma unroll 1
    for (int s = 0; s < 4; s++) {
        int buf = s & 1;
        cpasync_wait<0>();
        __syncthreads();
        if (s + 1 < 4) {
            load_stage(buf ^ 1, s + 1);
            cpasync_commit();
        }
        uint32_t sA = smem_u32(&As[buf][0]);
        uint32_t sB = smem_u32(&Bs[buf][0]);
        #pragma unroll
        for (int kk = 0; kk < 2; kk++) {
            int akoff = kk * 16 + ((lane >> 4) << 3);
            int lrow = lane & 15;
            uint32_t a[4][4];
            #pragma unroll
            for (int fi = 0; fi < 4; fi++) {
                uint32_t off = (uint32_t)(((64 * mw + 16 * fi + lrow) * LDA + akoff) * 2);
                ldsm4(a[fi], sA + off);
            }
            uint32_t b[4][2];
            #pragma unroll
            for (int fj2 = 0; fj2 < 2; fj2++) {
                uint32_t off = (uint32_t)(((32 * nw + 16 * fj2 + lrow) * LDA + akoff) * 2);
                uint32_t t[4];
                ldsm4(t, sB + off);
                b[2 * fj2][0] = t[0]; b[2 * fj2][1] = t[2];
                b[2 * fj2 + 1][0] = t[1]; b[2 * fj2 + 1][1] = t[3];
            }
            #pragma unroll
            for (int fi = 0; fi < 4; fi++)
                #pragma unroll
                for (int fj = 0; fj < 4; fj++)
                    mma16816f(acc[fi][fj], a[fi], b[fj]);
        }
        __syncthreads();
    }

    #pragma unroll
    for (int fi = 0; fi < 4; fi++) {
        #pragma unroll
        for (int fj = 0; fj < 4; fj++) {
            int mrow = row0 + 64 * mw + 16 * fi + (lane >> 2);
            int col  = 32 * nw + 8 * fj + 2 * (lane & 3);
            #pragma unroll
            for (int h = 0; h < 2; h++) {
                int r = mrow + 8 * h;
                if (r < NN) {
                    int cg = rbase + col;
                    float v0 = acc[fi][fj][2 * h + 0];
                    float v1 = acc[fi][fj][2 * h + 1];
                    if (cg < 64) { v0 += bias[cg]; v1 += bias[cg + 1]; }
                    *(__half2*)(out + (size_t)r * 256 + cg) = __floats2half2_rn(v0, v1);
                }
            }
        }
    }
}

// ====================== SpMM width 64 fp16, MLP-4, fused add ================

template <int F32OUT>
__global__ void __launch_bounds__(256)
k_spmm64h(const __half* __restrict__ fin, int sIn,
          const __half* __restrict__ addv, int sAdd,
          void* __restrict__ fout, int sOut) {
    int gw = (blockIdx.x * blockDim.x + threadIdx.x) >> 5;
    int lane = threadIdx.x & 31;
    if (gw >= NN) return;
    int beg = g_rp[gw], end = g_rp[gw + 1];
    float2 acc = make_float2(0.f, 0.f);
    int e = beg;
    for (; e + 4 <= end; e += 4) {
        int2 p0 = __ldg(&g_csr[e + 0]);
        int2 p1 = __ldg(&g_csr[e + 1]);
        int2 p2 = __ldg(&g_csr[e + 2]);
        int2 p3 = __ldg(&g_csr[e + 3]);
        __half2 h0 = __ldg((const __half2*)(fin + (size_t)p0.x * sIn) + lane);
        __half2 h1 = __ldg((const __half2*)(fin + (size_t)p1.x * sIn) + lane);
        __half2 h2 = __ldg((const __half2*)(fin + (size_t)p2.x * sIn) + lane);
        __half2 h3 = __ldg((const __half2*)(fin + (size_t)p3.x * sIn) + lane);
        float2 v0 = __half22float2(h0), v1 = __half22float2(h1);
        float2 v2 = __half22float2(h2), v3 = __half22float2(h3);
        float w0 = __int_as_float(p0.y), w1 = __int_as_float(p1.y);
        float w2 = __int_as_float(p2.y), w3 = __int_as_float(p3.y);
        acc.x = fmaf(w0, v0.x, acc.x); acc.y = fmaf(w0, v0.y, acc.y);
        acc.x = fmaf(w1, v1.x, acc.x); acc.y = fmaf(w1, v1.y, acc.y);
        acc.x = fmaf(w2, v2.x, acc.x); acc.y = fmaf(w2, v2.y, acc.y);
        acc.x = fmaf(w3, v3.x, acc.x); acc.y = fmaf(w3, v3.y, acc.y);
    }
    for (; e < end; e++) {
        int2 p = __ldg(&g_csr[e]);
        float w = __int_as_float(p.y);
        float2 v = __half22float2(__ldg((const __half2*)(fin + (size_t)p.x * sIn) + lane));
        acc.x = fmaf(w, v.x, acc.x);
        acc.y = fmaf(w, v.y, acc.y);
    }
    float2 a = __half22float2(__ldg((const __half2*)(addv + (size_t)gw * sAdd) + lane));
    acc.x += a.x; acc.y += a.y;
    if (F32OUT) {
        ((float2*)((float*)fout + (size_t)gw * sOut))[lane] = acc;
    } else {
        ((__half2*)((__half*)fout + (size_t)gw * sOut))[lane] = __floats2half2_rn(acc.x, acc.y);
    }
}

// ====================== predictor MLP ======================

__global__ void __launch_bounds__(256)
k_pred(const int* __restrict__ ps, const int* __restrict__ pd,
       const int* __restrict__ ns, const int* __restrict__ nd,
       const float* __restrict__ h,
       const float* __restrict__ P1, const float* __restrict__ pb1,
       const float* __restrict__ P2, const float* __restrict__ pb2,
       const float* __restrict__ P3, const float* __restrict__ pb3,
       float* __restrict__ out) {
    __shared__ float zs[8][64];
    __shared__ float a1s[8][32];
    int warp = (blockIdx.x * blockDim.x + threadIdx.x) >> 5;
    int lane = threadIdx.x & 31;
    int wl   = (threadIdx.x >> 5) & 7;
    if (warp >= 2 * PP) return;
    int s, d;
    if (warp < PP) { s = ps[warp]; d = pd[warp]; }
    else           { s = ns[warp - PP]; d = nd[warp - PP]; }

    const float* hs = h + (size_t)s * 64;
    const float* hd = h + (size_t)d * 64;
    zs[wl][lane]      = hs[lane]      * hd[lane];
    zs[wl][lane + 32] = hs[lane + 32] * hd[lane + 32];
    __syncwarp();

    float a = pb1[lane];
    #pragma unroll
    for (int k = 0; k < 64; k++) a = fmaf(zs[wl][k], P1[k * 32 + lane], a);
    a = a > 0.f ? a : 0.2f * a;
    a1s[wl][lane] = a;
    __syncwarp();

    float v = 0.f;
    if (lane < 16) {
        v = pb2[lane];
        #pragma unroll
        for (int k = 0; k < 32; k++) v = fmaf(a1s[wl][k], P2[k * 16 + lane], v);
        v = v > 0.f ? v : 0.2f * v;
        v *= P3[lane];
    }
    #pragma unroll
    for (int off = 8; off; off >>= 1) v += __shfl_down_sync(0xffffffffu, v, off);
    if (lane == 0) out[warp] = v + pb3[0];
}

// ====================== host ======================

extern "C" void kernel_launch(void* const* d_in, const int* in_sizes, int n_in,
                              void* d_out, int out_size) {
    const float* x       = (const float*)d_in[0];
    const int*   src     = (const int*)d_in[1];
    const int*   dst     = (const int*)d_in[2];
    const float* w_edge  = (const float*)d_in[3];
    const int*   pos_src = (const int*)d_in[4];
    const int*   pos_dst = (const int*)d_in[5];
    const int*   neg_src = (const int*)d_in[6];
    const int*   neg_dst = (const int*)d_in[7];
    const float* W1 = (const float*)d_in[8];
    const float* b1 = (const float*)d_in[9];
    const float* W2 = (const float*)d_in[10];
    const float* b2 = (const float*)d_in[11];
    const float* W3 = (const float*)d_in[12];
    const float* b3 = (const float*)d_in[13];
    const float* P1 = (const float*)d_in[14];
    const float* pb1 = (const float*)d_in[15];
    const float* P2 = (const float*)d_in[16];
    const float* pb2 = (const float*)d_in[17];
    const float* P3 = (const float*)d_in[18];
    const float* pb3 = (const float*)d_in[19];
    float* out = (float*)d_out;

    void *p_cnt, *p_x16, *p_hop1, *p_hop2, *p_hop3, *p_hA, *p_hB, *p_g;
    void *p_w1, *p_w2, *p_w3;
    cudaGetSymbolAddress(&p_cnt,  g_cnt);
    cudaGetSymbolAddress(&p_x16,  g_x16);
    cudaGetSymbolAddress(&p_hop1, g_hop1);
    cudaGetSymbolAddress(&p_hop2, g_hop2);
    cudaGetSymbolAddress(&p_hop3, g_hop3);
    cudaGetSymbolAddress(&p_hA,   g_hA);
    cudaGetSymbolAddress(&p_hB,   g_hB);
    cudaGetSymbolAddress(&p_g,    g_g);
    cudaGetSymbolAddress(&p_w1,   g_wt1);
    cudaGetSymbolAddress(&p_w2,   g_wt2);
    cudaGetSymbolAddress(&p_w3,   g_wt3);
    __half* x16  = (__half*)p_x16;
    __half* hop1 = (__half*)p_hop1;
    __half* hop2 = (__half*)p_hop2;
    __half* hop3 = (__half*)p_hop3;
    __half* hA   = (__half*)p_hA;
    __half* hB   = (__half*)p_hB;
    __half* gg   = (__half*)p_g;
    __half* w1   = (__half*)p_w1;
    __half* w2   = (__half*)p_w2;
    __half* w3   = (__half*)p_w3;
    float* hfin = out + 2 * PP;

    const int EB = (EE + 255) / 256;
    const int WG = (NN * 32 + 255) / 256;
    const int MT = (NN + 127) / 128;       // 391
    const int GRID_F = MTG + HOPB;         // 7032

    // preprocessing (4 launches incl. memset)
    cudaMemsetAsync(p_cnt, 0, (2 * NN + 64) * sizeof(int));
    k_prep2<<<(NN * 32 + 255) / 256, 256>>>(x, W1, W2, W3, dst);
    k_scanchain<<<(NN + 1023) / 1024, 1024>>>();
    k_scatter<<<EB, 256>>>(src, dst, w_edge);

    // layer 1: hops overlapped with partial GEMM chunks
    k_hopgemm<1><<<GRID_F, 256>>>(x16,  hop1, x16,  w1, 0);
    k_hopgemm<0><<<GRID_F, 256>>>(hop1, hop2, hop1, w1, 128);
    k_hopgemm<0><<<GRID_F, 256>>>(hop2, hop3, hop2, w1, 256);
    k_mfinal<<<MT, 256>>>(hop3, w1, 384, b1, hA);
    // layer 2
    k_hopgemm<1><<<GRID_F, 256>>>(hA,   hop1, hA,   w2, 0);
    k_hopgemm<0><<<GRID_F, 256>>>(hop1, hop2, hop1, w2, 128);
    k_hopgemm<0><<<GRID_F, 256>>>(hop2, hop3, hop2, w2, 256);
    k_mfinal<<<MT, 256>>>(hop3, w2, 384, b2, hB);
    // layer 3 (Horner)
    k_mgemm3<<<dim3(MT, 2), 256>>>(hB, w3, b3, gg);
    k_spmm64h<0><<<WG, 256>>>(gg + 192, 256, gg + 128, 256, hop1, 64);
    k_spmm64h<0><<<WG, 256>>>(hop1, 64,    gg + 64,  256, hop2, 64);
    k_spmm64h<1><<<WG, 256>>>(hop2, 64,    gg,       256, hfin, 64);

    // predictor
    k_pred<<<(2 * PP) / 8, 256>>>(pos_src, pos_dst, neg_src, neg_dst, hfin,
                                  P1, pb1, P2, pb2, P3, pb3, out);
}

// round 11
// speedup vs baseline: 1.4141x; 1.4141x over previous
#include <cuda_runtime.h>
#include <cuda_bf16.h>
#include <cuda_fp16.h>
#include <math.h>
#include <cstdint>

#define NN   50000
#define EE   800000
#define PP   65536
#define LDA  40

// ====================== scratch ======================

__device__ int   g_cnt[2 * NN + 64];      // [0,NN)=deg, [NN,2NN)=fill, [2NN,+64)=chain
__device__ float g_dn[NN];
__device__ int   g_rp[NN + 1];
__device__ __align__(16) int2 g_csr[EE];
__device__ __align__(16) __half g_x16 [NN * 128];
__device__ __align__(16) __half g_hop1[NN * 128];
__device__ __align__(16) __half g_hop2[NN * 128];
__device__ __align__(16) __half g_hop3[NN * 128];
__device__ __align__(16) __half g_hA  [NN * 128];
__device__ __align__(16) __half g_hB  [NN * 128];
__device__ __align__(16) __half g_g   [NN * 256];
__device__ __align__(16) __half g_wt1[65536];
__device__ __align__(16) __half g_wt2[65536];
__device__ __align__(16) __half g_wt3[32768];

// ====================== helpers ======================

__device__ __forceinline__ uint32_t smem_u32(const void* p) {
    uint32_t a;
    asm("{ .reg .u64 t; cvta.to.shared.u64 t, %1; cvt.u32.u64 %0, t; }" : "=r"(a) : "l"(p));
    return a;
}

__device__ __forceinline__ void ldsm4(uint32_t* r, uint32_t addr) {
    asm volatile("ldmatrix.sync.aligned.m8n8.x4.shared.b16 {%0,%1,%2,%3}, [%4];"
                 : "=r"(r[0]), "=r"(r[1]), "=r"(r[2]), "=r"(r[3]) : "r"(addr));
}

__device__ __forceinline__ void mma16816f(float* c, const uint32_t* a, const uint32_t* b) {
    asm volatile(
        "mma.sync.aligned.m16n8k16.row.col.f32.f16.f16.f32 "
        "{%0,%1,%2,%3}, {%4,%5,%6,%7}, {%8,%9}, {%0,%1,%2,%3};"
        : "+f"(c[0]), "+f"(c[1]), "+f"(c[2]), "+f"(c[3])
        : "r"(a[0]), "r"(a[1]), "r"(a[2]), "r"(a[3]), "r"(b[0]), "r"(b[1]));
}

__device__ __forceinline__ void cpasync16(uint32_t saddr, const void* gptr) {
    asm volatile("cp.async.cg.shared.global [%0], [%1], 16;" :: "r"(saddr), "l"(gptr));
}
__device__ __forceinline__ void cpasync_commit() {
    asm volatile("cp.async.commit_group;" ::: "memory");
}
template <int N>
__device__ __forceinline__ void cpasync_wait() {
    asm volatile("cp.async.wait_group %0;" :: "n"(N) : "memory");
}

// ====================== launch 2: prep + hist fused ======================

__global__ void k_prep2(const float* __restrict__ x,
                        const float* __restrict__ W1, const float* __restrict__ W2,
                        const float* __restrict__ W3, const int* __restrict__ dst) {
    int gid = blockIdx.x * 256 + threadIdx.x;
    if (gid < EE) atomicAdd(&g_cnt[dst[gid]], 1);
    if (gid < 65536) {
        int n = gid >> 9, k = gid & 511;
        g_wt1[gid] = __float2half_rn(W1[k * 128 + n]);
    } else if (gid < 131072) {
        int idx = gid - 65536;
        int n = idx >> 9, k = idx & 511;
        g_wt2[idx] = __float2half_rn(W2[k * 128 + n]);
    } else if (gid < 163840) {
        int idx = gid - 131072;
        int r = idx >> 7, k = idx & 127;
        int j = r >> 6, n = r & 63;
        g_wt3[idx] = __float2half_rn(W3[(j * 128 + k) * 64 + n]);
    }
    if (gid < NN * 32) {
        float4 v = __ldg((const float4*)x + gid);
        __half2 a = __floats2half2_rn(v.x, v.y);
        __half2 b = __floats2half2_rn(v.z, v.w);
        ((uint2*)g_x16)[gid] = make_uint2(*(uint32_t*)&a, *(uint32_t*)&b);
    }
}

// ====================== launch 3: single-pass chained scan + dn ============

__global__ void __launch_bounds__(1024)
k_scanchain() {
    __shared__ int s[1024];
    __shared__ int sprev;
    volatile int* chain = (volatile int*)(g_cnt + 2 * NN);
    int b = blockIdx.x;
    int i = b * 1024 + threadIdx.x;
    int v = (i < NN) ? g_cnt[i] : 0;
    s[threadIdx.x] = v;
    __syncthreads();
    #pragma unroll
    for (int off = 1; off < 1024; off <<= 1) {
        int t = (threadIdx.x >= off) ? s[threadIdx.x - off] : 0;
        __syncthreads();
        s[threadIdx.x] += t;
        __syncthreads();
    }
    if (threadIdx.x == 0) {
        int prev = 0;
        if (b > 0) {
            int t;
            do { t = chain[b - 1]; } while (t == 0);
            prev = t - 1;
        }
        sprev = prev;
        __threadfence();
        chain[b] = prev + s[1023] + 1;
    }
    __syncthreads();
    int prev = sprev;
    if (i < NN) {
        g_rp[i + 1] = s[threadIdx.x] + prev;
        if (i == 0) g_rp[0] = 0;
        int d = (v < 1) ? 1 : v;
        g_dn[i] = rsqrtf((float)d);
    }
}

// ====================== launch 4: scatter to interleaved CSR ================

__global__ void k_scatter(const int* __restrict__ src, const int* __restrict__ dst,
                          const float* __restrict__ w) {
    int e = blockIdx.x * blockDim.x + threadIdx.x;
    if (e >= EE) return;
    int s = src[e], d = dst[e];
    int slot = g_rp[d] + atomicAdd(&g_cnt[NN + d], 1);
    float cw = w[e] * g_dn[s] * g_dn[d];
    g_csr[slot] = make_int2(s, __float_as_int(cw));
}

// ====================== SpMM width 128 fp16, MLP-8 edge loop ================

__global__ void __launch_bounds__(256)
k_spmmh(const __half* __restrict__ fin, __half* __restrict__ fout) {
    int gw = (blockIdx.x * blockDim.x + threadIdx.x) >> 5;
    int lane = threadIdx.x & 31;
    if (gw >= NN) return;
    int beg = g_rp[gw], end = g_rp[gw + 1];
    const uint2* in = (const uint2*)fin;
    float4 acc = make_float4(0.f, 0.f, 0.f, 0.f);
    int e = beg;
    for (; e + 8 <= end; e += 8) {
        int2 p[8];
        uint2 v[8];
        #pragma unroll
        for (int q = 0; q < 8; q++) p[q] = __ldg(&g_csr[e + q]);
        #pragma unroll
        for (int q = 0; q < 8; q++) v[q] = __ldg(&in[(size_t)p[q].x * 32 + lane]);
        #pragma unroll
        for (int q = 0; q < 8; q++) {
            float w = __int_as_float(p[q].y);
            float2 f0 = __half22float2(*(__half2*)&v[q].x);
            float2 f1 = __half22float2(*(__half2*)&v[q].y);
            acc.x = fmaf(w, f0.x, acc.x);
            acc.y = fmaf(w, f0.y, acc.y);
            acc.z = fmaf(w, f1.x, acc.z);
            acc.w = fmaf(w, f1.y, acc.w);
        }
    }
    if (e + 4 <= end) {
        int2 p[4];
        uint2 v[4];
        #pragma unroll
        for (int q = 0; q < 4; q++) p[q] = __ldg(&g_csr[e + q]);
        #pragma unroll
        for (int q = 0; q < 4; q++) v[q] = __ldg(&in[(size_t)p[q].x * 32 + lane]);
        #pragma unroll
        for (int q = 0; q < 4; q++) {
            float w = __int_as_float(p[q].y);
            float2 f0 = __half22float2(*(__half2*)&v[q].x);
            float2 f1 = __half22float2(*(__half2*)&v[q].y);
            acc.x = fmaf(w, f0.x, acc.x);
            acc.y = fmaf(w, f0.y, acc.y);
            acc.z = fmaf(w, f1.x, acc.z);
            acc.w = fmaf(w, f1.y, acc.w);
        }
        e += 4;
    }
    for (; e < end; e++) {
        int2 p = __ldg(&g_csr[e]);
        float w = __int_as_float(p.y);
        uint2 v = __ldg(&in[(size_t)p.x * 32 + lane]);
        float2 f0 = __half22float2(*(__half2*)&v.x);
        float2 f1 = __half22float2(*(__half2*)&v.y);
        acc.x = fmaf(w, f0.x, acc.x);
        acc.y = fmaf(w, f0.y, acc.y);
        acc.z = fmaf(w, f1.x, acc.z);
        acc.w = fmaf(w, f1.y, acc.w);
    }
    __half2 o0 = __floats2half2_rn(acc.x, acc.y);
    __half2 o1 = __floats2half2_rn(acc.z, acc.w);
    ((uint2*)fout)[(size_t)gw * 32 + lane] = make_uint2(*(uint32_t*)&o0, *(uint32_t*)&o1);
}

// ====================== SpMM width 64 fp16, MLP-8, fused add ================

template <int F32OUT>
__global__ void __launch_bounds__(256)
k_spmm64h(const __half* __restrict__ fin, int sIn,
          const __half* __restrict__ addv, int sAdd,
          void* __restrict__ fout, int sOut) {
    int gw = (blockIdx.x * blockDim.x + threadIdx.x) >> 5;
    int lane = threadIdx.x & 31;
    if (gw >= NN) return;
    int beg = g_rp[gw], end = g_rp[gw + 1];
    float2 acc = make_float2(0.f, 0.f);
    int e = beg;
    for (; e + 8 <= end; e += 8) {
        int2 p[8];
        __half2 v[8];
        #pragma unroll
        for (int q = 0; q < 8; q++) p[q] = __ldg(&g_csr[e + q]);
        #pragma unroll
        for (int q = 0; q < 8; q++)
            v[q] = __ldg((const __half2*)(fin + (size_t)p[q].x * sIn) + lane);
        #pragma unroll
        for (int q = 0; q < 8; q++) {
            float w = __int_as_float(p[q].y);
            float2 f = __half22float2(v[q]);
            acc.x = fmaf(w, f.x, acc.x);
            acc.y = fmaf(w, f.y, acc.y);
        }
    }
    for (; e < end; e++) {
        int2 p = __ldg(&g_csr[e]);
        float w = __int_as_float(p.y);
        float2 v = __half22float2(__ldg((const __half2*)(fin + (size_t)p.x * sIn) + lane));
        acc.x = fmaf(w, v.x, acc.x);
        acc.y = fmaf(w, v.y, acc.y);
    }
    float2 a = __half22float2(__ldg((const __half2*)(addv + (size_t)gw * sAdd) + lane));
    acc.x += a.x; acc.y += a.y;
    if (F32OUT) {
        ((float2*)((float*)fout + (size_t)gw * sOut))[lane] = acc;
    } else {
        ((__half2*)((__half*)fout + (size_t)gw * sOut))[lane] = __floats2half2_rn(acc.x, acc.y);
    }
}

// ====================== fp16 HMMA GEMM, cp.async 2-stage pipeline ==========
// CTA tile 128x128; 8 warps 2(M)x4(N); warp tile 64x32.
// MODE 0: out = relu(d + bias[c]) fp16, grid.y=1
// MODE 1: out[r*256+by*128+c] = d + (col<64 ? bias[col] : 0) fp16, grid.y=2

template <int KTOT, int MODE>
__global__ void __launch_bounds__(256, 1)
k_mgemm(const __half* __restrict__ f0, const __half* __restrict__ f1,
        const __half* __restrict__ f2, const __half* __restrict__ f3,
        const __half* __restrict__ Wt,
        const float* __restrict__ bias, __half* __restrict__ out) {
    __shared__ __half As[2][128 * LDA];
    __shared__ __half Bs[2][128 * LDA];

    const __half* bases[4] = {f0, f1, f2, f3};
    int tid = threadIdx.x, warp = tid >> 5, lane = tid & 31;
    int mw = warp & 1, nw = warp >> 1;
    int row0 = blockIdx.x * 128;
    int rbase = (MODE == 1) ? blockIdx.y * 128 : 0;

    int ar0 = tid >> 2, aj0 = tid & 3;
    int ar1 = (tid + 256) >> 2, aj1 = tid & 3;

    float acc[4][4][4];
    #pragma unroll
    for (int i = 0; i < 4; i++)
        #pragma unroll
        for (int j = 0; j < 4; j++)
            #pragma unroll
            for (int q = 0; q < 4; q++) acc[i][j][q] = 0.f;

    const int NSTEP = KTOT / 32;

    auto load_stage = [&](int buf, int s) {
        const __half* Ab = bases[(s * 32) >> 7];
        int coloff = (s * 32) & 127;
        uint32_t sA = smem_u32(&As[buf][0]);
        uint32_t sB = smem_u32(&Bs[buf][0]);
        int g0 = row0 + ar0; if (g0 > NN - 1) g0 = NN - 1;
        int g1 = row0 + ar1; if (g1 > NN - 1) g1 = NN - 1;
        cpasync16(sA + (uint32_t)(ar0 * LDA + aj0 * 8) * 2,
                  Ab + (size_t)g0 * 128 + coloff + aj0 * 8);
        cpasync16(sA + (uint32_t)(ar1 * LDA + aj1 * 8) * 2,
                  Ab + (size_t)g1 * 128 + coloff + aj1 * 8);
        cpasync16(sB + (uint32_t)(ar0 * LDA + aj0 * 8) * 2,
                  Wt + (size_t)(rbase + ar0) * KTOT + s * 32 + aj0 * 8);
        cpasync16(sB + (uint32_t)(ar1 * LDA + aj1 * 8) * 2,
                  Wt + (size_t)(rbase + ar1) * KTOT + s * 32 + aj1 * 8);
    };

    load_stage(0, 0);
    cpasync_commit();

    #pragma unroll 1
    for (int s = 0; s < NSTEP; s++) {
        int buf = s & 1;
        cpasync_wait<0>();
        __syncthreads();
        if (s + 1 < NSTEP) {
            load_stage(buf ^ 1, s + 1);
            cpasync_commit();
        }

        uint32_t sA = smem_u32(&As[buf][0]);
        uint32_t sB = smem_u32(&Bs[buf][0]);
        #pragma unroll
        for (int kk = 0; kk < 2; kk++) {
            int akoff = kk * 16 + ((lane >> 4) << 3);
            int lrow = lane & 15;
            uint32_t a[4][4];
            #pragma unroll
            for (int fi = 0; fi < 4; fi++) {
                uint32_t off = (uint32_t)(((64 * mw + 16 * fi + lrow) * LDA + akoff) * 2);
                ldsm4(a[fi], sA + off);
            }
            uint32_t b[4][2];
            #pragma unroll
            for (int fj2 = 0; fj2 < 2; fj2++) {
                uint32_t off = (uint32_t)(((32 * nw + 16 * fj2 + lrow) * LDA + akoff) * 2);
                uint32_t t[4];
                ldsm4(t, sB + off);
                b[2 * fj2][0] = t[0]; b[2 * fj2][1] = t[2];
                b[2 * fj2 + 1][0] = t[1]; b[2 * fj2 + 1][1] = t[3];
            }
            #pragma unroll
            for (int fi = 0; fi < 4; fi++)
                #pragma unroll
                for (int fj = 0; fj < 4; fj++)
                    mma16816f(acc[fi][fj], a[fi], b[fj]);
        }
        __syncthreads();
    }

    #pragma unroll
    for (int fi = 0; fi < 4; fi++) {
        #pragma unroll
        for (int fj = 0; fj < 4; fj++) {
            int mrow = row0 + 64 * mw + 16 * fi + (lane >> 2);
            int col  = 32 * nw + 8 * fj + 2 * (lane & 3);
            #pragma unroll
            for (int h = 0; h < 2; h++) {
                int r = mrow + 8 * h;
                if (r < NN) {
                    float v0 = acc[fi][fj][2 * h + 0];
                    float v1 = acc[fi][fj][2 * h + 1];
                    if (MODE == 0) {
                        v0 += bias[col];     v1 += bias[col + 1];
                        v0 = v0 > 0.f ? v0 : 0.f;
                        v1 = v1 > 0.f ? v1 : 0.f;
                        *(__half2*)(out + (size_t)r * 128 + col) = __floats2half2_rn(v0, v1);
                    } else {
                        int cg = blockIdx.y * 128 + col;
                        if (cg < 64) { v0 += bias[cg]; v1 += bias[cg + 1]; }
                        *(__half2*)(out + (size_t)r * 256 + cg) = __floats2half2_rn(v0, v1);
                    }
                }
            }
        }
    }
}

// ====================== predictor MLP ======================

__global__ void __launch_bounds__(256)
k_pred(const int* __restrict__ ps, const int* __restrict__ pd,
       const int* __restrict__ ns, const int* __restrict__ nd,
       const float* __restrict__ h,
       const float* __restrict__ P1, const float* __restrict__ pb1,
       const float* __restrict__ P2, const float* __restrict__ pb2,
       const float* __restrict__ P3, const float* __restrict__ pb3,
       float* __restrict__ out) {
    __shared__ float zs[8][64];
    __shared__ float a1s[8][32];
    int warp = (blockIdx.x * blockDim.x + threadIdx.x) >> 5;
    int lane = threadIdx.x & 31;
    int wl   = (threadIdx.x >> 5) & 7;
    if (warp >= 2 * PP) return;
    int s, d;
    if (warp < PP) { s = ps[warp]; d = pd[warp]; }
    else           { s = ns[warp - PP]; d = nd[warp - PP]; }

    const float* hs = h + (size_t)s * 64;
    const float* hd = h + (size_t)d * 64;
    zs[wl][lane]      = hs[lane]      * hd[lane];
    zs[wl][lane + 32] = hs[lane + 32] * hd[lane + 32];
    __syncwarp();

    float a = pb1[lane];
    #pragma unroll
    for (int k = 0; k < 64; k++) a = fmaf(zs[wl][k], P1[k * 32 + lane], a);
    a = a > 0.f ? a : 0.2f * a;
    a1s[wl][lane] = a;
    __syncwarp();

    float v = 0.f;
    if (lane < 16) {
        v = pb2[lane];
        #pragma unroll
        for (int k = 0; k < 32; k++) v = fmaf(a1s[wl][k], P2[k * 16 + lane], v);
        v = v > 0.f ? v : 0.2f * v;
        v *= P3[lane];
    }
    #pragma unroll
    for (int off = 8; off; off >>= 1) v += __shfl_down_sync(0xffffffffu, v, off);
    if (lane == 0) out[warp] = v + pb3[0];
}

// ====================== host ======================

extern "C" void kernel_launch(void* const* d_in, const int* in_sizes, int n_in,
                              void* d_out, int out_size) {
    const float* x       = (const float*)d_in[0];
    const int*   src     = (const int*)d_in[1];
    const int*   dst     = (const int*)d_in[2];
    const float* w_edge  = (const float*)d_in[3];
    const int*   pos_src = (const int*)d_in[4];
    const int*   pos_dst = (const int*)d_in[5];
    const int*   neg_src = (const int*)d_in[6];
    const int*   neg_dst = (const int*)d_in[7];
    const float* W1 = (const float*)d_in[8];
    const float* b1 = (const float*)d_in[9];
    const float* W2 = (const float*)d_in[10];
    const float* b2 = (const float*)d_in[11];
    const float* W3 = (const float*)d_in[12];
    const float* b3 = (const float*)d_in[13];
    const float* P1 = (const float*)d_in[14];
    const float* pb1 = (const float*)d_in[15];
    const float* P2 = (const float*)d_in[16];
    const float* pb2 = (const float*)d_in[17];
    const float* P3 = (const float*)d_in[18];
    const float* pb3 = (const float*)d_in[19];
    float* out = (float*)d_out;

    void *p_cnt, *p_x16, *p_hop1, *p_hop2, *p_hop3, *p_hA, *p_hB, *p_g;
    void *p_w1, *p_w2, *p_w3;
    cudaGetSymbolAddress(&p_cnt,  g_cnt);
    cudaGetSymbolAddress(&p_x16,  g_x16);
    cudaGetSymbolAddress(&p_hop1, g_hop1);
    cudaGetSymbolAddress(&p_hop2, g_hop2);
    cudaGetSymbolAddress(&p_hop3, g_hop3);
    cudaGetSymbolAddress(&p_hA,   g_hA);
    cudaGetSymbolAddress(&p_hB,   g_hB);
    cudaGetSymbolAddress(&p_g,    g_g);
    cudaGetSymbolAddress(&p_w1,   g_wt1);
    cudaGetSymbolAddress(&p_w2,   g_wt2);
    cudaGetSymbolAddress(&p_w3,   g_wt3);
    __half* x16  = (__half*)p_x16;
    __half* hop1 = (__half*)p_hop1;
    __half* hop2 = (__half*)p_hop2;
    __half* hop3 = (__half*)p_hop3;
    __half* hA   = (__half*)p_hA;
    __half* hB   = (__half*)p_hB;
    __half* gg   = (__half*)p_g;
    __half* w1   = (__half*)p_w1;
    __half* w2   = (__half*)p_w2;
    __half* w3   = (__half*)p_w3;
    float* hfin = out + 2 * PP;

    const int EB = (EE + 255) / 256;
    const int WG = (NN * 32 + 255) / 256;
    const int MT = (NN + 127) / 128;

    // preprocessing (4 launches incl. memset)
    cudaMemsetAsync(p_cnt, 0, (2 * NN + 64) * sizeof(int));
    k_prep2<<<(NN * 32 + 255) / 256, 256>>>(x, W1, W2, W3, dst);
    k_scanchain<<<(NN + 1023) / 1024, 1024>>>();
    k_scatter<<<EB, 256>>>(src, dst, w_edge);

    // layer 1
    k_spmmh<<<WG, 256>>>(x16, hop1);
    k_spmmh<<<WG, 256>>>(hop1, hop2);
    k_spmmh<<<WG, 256>>>(hop2, hop3);
    k_mgemm<512, 0><<<dim3(MT, 1), 256>>>(x16, hop1, hop2, hop3, w1, b1, hA);
    // layer 2
    k_spmmh<<<WG, 256>>>(hA, hop1);
    k_spmmh<<<WG, 256>>>(hop1, hop2);
    k_spmmh<<<WG, 256>>>(hop2, hop3);
    k_mgemm<512, 0><<<dim3(MT, 1), 256>>>(hA, hop1, hop2, hop3, w2, b2, hB);
    // layer 3 (Horner)
    k_mgemm<128, 1><<<dim3(MT, 2), 256>>>(hB, hB, hB, hB, w3, b3, gg);
    k_spmm64h<0><<<WG, 256>>>(gg + 192, 256, gg + 128, 256, hop1, 64);
    k_spmm64h<0><<<WG, 256>>>(hop1, 64,    gg + 64,  256, hop2, 64);
    k_spmm64h<1><<<WG, 256>>>(hop2, 64,    gg,       256, hfin, 64);

    // predictor
    k_pred<<<(2 * PP) / 8, 256>>>(pos_src, pos_dst, neg_src, neg_dst, hfin,
                                  P1, pb1, P2, pb2, P3, pb3, out);
}